// round 1
// baseline (speedup 1.0000x reference)
#include <cuda_runtime.h>
#include <cstdint>

#define N_  4096
#define D_  128
#define R_  256
#define O_  64

// Scratch (static __device__ — no allocation at runtime, per harness rules)
__device__ float g_wT[D_ * R_];          // w = 1/(2*sigma^2), transposed [d][r]
__device__ float g_uT[D_ * R_];          // u = c/sigma^2,     transposed [d][r]
__device__ float g_k[R_];                // k[r] = sum_d w*c^2
__device__ float g_norm[(size_t)N_ * R_];            // normalized strengths [n][r]  (4 MB)
__device__ float g_partial[8][(size_t)N_ * O_];      // per-rule-split logits partials (8 MB)

typedef unsigned long long ull;

__device__ __forceinline__ ull pack2(float lo, float hi) {
    ull r; asm("mov.b64 %0, {%1, %2};" : "=l"(r) : "f"(lo), "f"(hi)); return r;
}
__device__ __forceinline__ void unpack2(ull v, float& lo, float& hi) {
    asm("mov.b64 {%0, %1}, %2;" : "=f"(lo), "=f"(hi) : "l"(v));
}
// d = a*b + c  on packed f32x2 (Blackwell FFMA2 — PTX-only path)
__device__ __forceinline__ ull fma2(ull a, ull b, ull c) {
    ull d; asm("fma.rn.f32x2 %0, %1, %2, %3;" : "=l"(d) : "l"(a), "l"(b), "l"(c)); return d;
}

// ---------------------------------------------------------------------------
// Kernel 1: parameter prep.  One block per rule r, 128 threads (one per d).
// ---------------------------------------------------------------------------
__global__ void prep_kernel(const float* __restrict__ centers,
                            const float* __restrict__ sigmas) {
    int r = blockIdx.x;
    int d = threadIdx.x;
    float c  = centers[r * D_ + d];
    float sg = sigmas [r * D_ + d];
    float inv = 1.0f / (sg * sg);
    float w = 0.5f * inv;
    float u = c * inv;
    g_wT[d * R_ + r] = w;
    g_uT[d * R_ + r] = u;
    __shared__ float red[128];
    red[d] = w * c * c;
    __syncthreads();
    for (int s = 64; s > 0; s >>= 1) {
        if (d < s) red[d] += red[d + s];
        __syncthreads();
    }
    if (d == 0) g_k[r] = red[0];
}

// ---------------------------------------------------------------------------
// Kernel 2: strengths + normalization. One block per 32 rows of X.
// 256 threads; thread t owns rule r=t for all 32 rows.
//   log-strength s[n] = sum_d (u - w*x)*x  - k[r]
// Then exp, block-wide row-sum over r, normalize, store g_norm.
// ---------------------------------------------------------------------------
__global__ void __launch_bounds__(256) strengths_kernel(const float* __restrict__ X) {
    extern __shared__ float sm[];
    float* Xs   = sm;                       // [128][32]  (d-major), 16 KB
    float* E    = Xs + 128 * 32;            // [32][257]  strengths, padded stride
    float* P    = E  + 32 * 257;            // [32][9]    partial row sums
    float* Sinv = P  + 32 * 9;              // [32]

    const int tid = threadIdx.x;            // rule index
    const int nb  = blockIdx.x * 32;

    // Load X tile transposed: Xs[d][n] = X[nb+n][d]
    for (int idx = tid; idx < 32 * 128; idx += 256) {
        int n = idx >> 7, d = idx & 127;
        Xs[d * 32 + n] = X[(size_t)(nb + n) * D_ + d];
    }
    __syncthreads();

    const int r = tid;
    float kk = g_k[r];
    ull s[16];
    ull init = pack2(-kk, -kk);
    #pragma unroll
    for (int p = 0; p < 16; ++p) s[p] = init;

    for (int d = 0; d < 128; ++d) {
        float w = g_wT[d * R_ + r];
        float u = g_uT[d * R_ + r];
        ull w2 = pack2(-w, -w);
        ull u2 = pack2(u, u);
        const float* xrow = &Xs[d * 32];
        #pragma unroll
        for (int p = 0; p < 16; ++p) {
            ull xp = *(const ull*)&xrow[p * 2];     // two n's x values (broadcast LDS)
            ull t  = fma2(w2, xp, u2);              // u - w*x
            s[p]   = fma2(t, xp, s[p]);             // += (u - w*x)*x
        }
    }

    float e[32];
    #pragma unroll
    for (int p = 0; p < 16; ++p) {
        float a, b;
        unpack2(s[p], a, b);
        e[2 * p]     = expf(a);
        e[2 * p + 1] = expf(b);
        E[(2 * p)     * 257 + r] = e[2 * p];
        E[(2 * p + 1) * 257 + r] = e[2 * p + 1];
    }
    __syncthreads();

    // Row sums over 256 rules: 8 partials per row
    {
        int n = tid >> 3, c = tid & 7;
        float ps = 0.0f;
        const float* row = &E[n * 257 + c * 32];
        #pragma unroll
        for (int k2 = 0; k2 < 32; ++k2) ps += row[k2];
        P[n * 9 + c] = ps;
    }
    __syncthreads();
    if (tid < 32) {
        float s0 = 0.0f;
        #pragma unroll
        for (int c = 0; c < 8; ++c) s0 += P[tid * 9 + c];
        Sinv[tid] = 1.0f / (s0 + 1e-8f);
    }
    __syncthreads();

    #pragma unroll
    for (int n = 0; n < 32; ++n)
        g_norm[(size_t)(nb + n) * R_ + r] = e[n] * Sinv[n];
}

// ---------------------------------------------------------------------------
// Kernel 3: main combine.  Block = 64 rows x 32 rules (grid 64 x 8).
// out_partial[n][j] = sum_{r in chunk} norm[n][r] * ( X[n,:].C_r[:,j] + b_r[j] )
// f32x2 outer-product microkernel: thread tile 4n x 4j (= 4n x 2 pairs).
// ---------------------------------------------------------------------------
__global__ void __launch_bounds__(256) main_kernel(const float* __restrict__ X,
                                                   const float* __restrict__ coeffs) {
    extern __shared__ float sm[];
    float* Xs = sm;                 // [128][64] transposed X tile  (32 KB)
    float* Cs = Xs + 128 * 64;      // [128][64] current rule coeffs (32 KB)
    float* Bs = Cs + 128 * 64;      // [64] bias
    float* Ns = Bs + 64;            // [64][32] norm tile (8 KB)

    const int tid = threadIdx.x;
    const int nb  = blockIdx.x * 64;
    const int rb  = blockIdx.y * 32;

    for (int idx = tid; idx < 64 * 128; idx += 256) {
        int n = idx >> 7, d = idx & 127;
        Xs[d * 64 + n] = X[(size_t)(nb + n) * D_ + d];
    }
    for (int idx = tid; idx < 64 * 32; idx += 256) {
        int n = idx >> 5, rl = idx & 31;
        Ns[idx] = g_norm[(size_t)(nb + n) * R_ + rb + rl];
    }

    const int tx = tid & 15;        // j group
    const int ty = tid >> 4;        // n group
    const int n0 = ty * 4;
    const int j0 = tx * 4;

    ull acc[4][2];
    #pragma unroll
    for (int a = 0; a < 4; ++a) { acc[a][0] = 0ull; acc[a][1] = 0ull; }

    for (int r = 0; r < 32; ++r) {
        const float* Cg = coeffs + (size_t)(rb + r) * (129 * 64);
        __syncthreads();    // covers initial Xs/Ns loads & prev-iter Cs reads
        for (int idx = tid; idx < 8192; idx += 256) Cs[idx] = Cg[idx];
        if (tid < 64) Bs[tid] = Cg[8192 + tid];
        __syncthreads();

        ull b0 = *(const ull*)&Bs[j0];
        ull b1 = *(const ull*)&Bs[j0 + 2];
        ull p[4][2];
        #pragma unroll
        for (int a = 0; a < 4; ++a) { p[a][0] = b0; p[a][1] = b1; }

        #pragma unroll 4
        for (int i = 0; i < 128; ++i) {
            float4 xv = *(const float4*)&Xs[i * 64 + n0];
            ull c0 = *(const ull*)&Cs[i * 64 + j0];
            ull c1 = *(const ull*)&Cs[i * 64 + j0 + 2];
            ull xx;
            xx = pack2(xv.x, xv.x); p[0][0] = fma2(xx, c0, p[0][0]); p[0][1] = fma2(xx, c1, p[0][1]);
            xx = pack2(xv.y, xv.y); p[1][0] = fma2(xx, c0, p[1][0]); p[1][1] = fma2(xx, c1, p[1][1]);
            xx = pack2(xv.z, xv.z); p[2][0] = fma2(xx, c0, p[2][0]); p[2][1] = fma2(xx, c1, p[2][1]);
            xx = pack2(xv.w, xv.w); p[3][0] = fma2(xx, c0, p[3][0]); p[3][1] = fma2(xx, c1, p[3][1]);
        }

        #pragma unroll
        for (int a = 0; a < 4; ++a) {
            float nv = Ns[(n0 + a) * 32 + r];
            ull nn = pack2(nv, nv);
            acc[a][0] = fma2(p[a][0], nn, acc[a][0]);
            acc[a][1] = fma2(p[a][1], nn, acc[a][1]);
        }
    }

    float* outp = g_partial[blockIdx.y];
    #pragma unroll
    for (int a = 0; a < 4; ++a) {
        float v0, v1, v2, v3;
        unpack2(acc[a][0], v0, v1);
        unpack2(acc[a][1], v2, v3);
        *(float4*)&outp[(size_t)(nb + n0 + a) * O_ + j0] = make_float4(v0, v1, v2, v3);
    }
}

// ---------------------------------------------------------------------------
// Kernel 4: reduce rule-split partials + softmax over O=64. Block per row.
// ---------------------------------------------------------------------------
__global__ void softmax_kernel(float* __restrict__ out) {
    int n = blockIdx.x;
    int j = threadIdx.x;           // 0..63
    float l = 0.0f;
    #pragma unroll
    for (int s = 0; s < 8; ++s) l += g_partial[s][(size_t)n * O_ + j];

    __shared__ float shm[2], shs[2];
    float m = l;
    #pragma unroll
    for (int o = 16; o > 0; o >>= 1) m = fmaxf(m, __shfl_xor_sync(0xffffffff, m, o));
    if ((j & 31) == 0) shm[j >> 5] = m;
    __syncthreads();
    m = fmaxf(shm[0], shm[1]);

    float e = expf(l - m);
    float ssum = e;
    #pragma unroll
    for (int o = 16; o > 0; o >>= 1) ssum += __shfl_xor_sync(0xffffffff, ssum, o);
    if ((j & 31) == 0) shs[j >> 5] = ssum;
    __syncthreads();
    float tot = shs[0] + shs[1];

    out[(size_t)n * O_ + j] = e / tot;
}

// ---------------------------------------------------------------------------
extern "C" void kernel_launch(void* const* d_in, const int* in_sizes, int n_in,
                              void* d_out, int out_size) {
    const float* X       = (const float*)d_in[0];
    const float* centers = (const float*)d_in[1];
    const float* sigmas  = (const float*)d_in[2];
    const float* coeffs  = (const float*)d_in[3];
    float* out = (float*)d_out;

    const int SMEM_S = (128 * 32 + 32 * 257 + 32 * 9 + 32) * (int)sizeof(float);   // ~50.6 KB
    const int SMEM_M = (128 * 64 + 128 * 64 + 64 + 64 * 32) * (int)sizeof(float);  // ~74 KB

    cudaFuncSetAttribute(strengths_kernel, cudaFuncAttributeMaxDynamicSharedMemorySize, SMEM_S);
    cudaFuncSetAttribute(main_kernel,      cudaFuncAttributeMaxDynamicSharedMemorySize, SMEM_M);

    prep_kernel<<<R_, D_>>>(centers, sigmas);
    strengths_kernel<<<N_ / 32, 256, SMEM_S>>>(X);
    main_kernel<<<dim3(N_ / 64, 8), 256, SMEM_M>>>(X, coeffs);
    softmax_kernel<<<N_, O_>>>(out);
}

// round 3
// speedup vs baseline: 1.1779x; 1.1779x over previous
#include <cuda_runtime.h>
#include <cstdint>

#define N_  4096
#define D_  128
#define R_  256
#define O_  64

// ---------------- scratch (__device__ globals; no runtime alloc) ------------
__device__ float g_wT[D_ * R_];
__device__ float g_uT[D_ * R_];
__device__ float g_k[R_];
__device__ float g_norm[(size_t)N_ * R_];              // [n][r]
__device__ float g_Bf[(size_t)R_ * 8192];              // fragment-packed coeffs (8 MB)
__device__ float g_Bbf[8 * 2048];                      // fragment-packed bias per split
__device__ float g_partial[8][(size_t)N_ * O_];        // per-split logits partials

typedef unsigned long long ull;

// ---------------- helpers ---------------------------------------------------
__device__ __forceinline__ ull pack2(float lo, float hi) {
    ull r; asm("mov.b64 %0, {%1, %2};" : "=l"(r) : "f"(lo), "f"(hi)); return r;
}
__device__ __forceinline__ void unpack2(ull v, float& lo, float& hi) {
    asm("mov.b64 {%0, %1}, %2;" : "=f"(lo), "=f"(hi) : "l"(v));
}
__device__ __forceinline__ ull fma2(ull a, ull b, ull c) {
    ull d; asm("fma.rn.f32x2 %0, %1, %2, %3;" : "=l"(d) : "l"(a), "l"(b), "l"(c)); return d;
}
__device__ __forceinline__ float tf32r(float x) {
    uint32_t u; asm("cvt.rna.tf32.f32 %0, %1;" : "=r"(u) : "f"(x));
    return __uint_as_float(u);
}

// m16n8k8 tf32 MMA (sm_80 path — available at compute_103 generic target)
__device__ __forceinline__ void mma_tf32(float* c,
                                         float a0, float a1, float a2, float a3,
                                         uint32_t b0, uint32_t b1) {
    asm volatile(
        "mma.sync.aligned.m16n8k8.row.col.f32.tf32.tf32.f32 "
        "{%0,%1,%2,%3}, {%4,%5,%6,%7}, {%8,%9}, {%0,%1,%2,%3};"
        : "+f"(c[0]), "+f"(c[1]), "+f"(c[2]), "+f"(c[3])
        : "r"(__float_as_uint(a0)), "r"(__float_as_uint(a1)),
          "r"(__float_as_uint(a2)), "r"(__float_as_uint(a3)),
          "r"(b0), "r"(b1));
}

// ---------------------------------------------------------------------------
// Kernel 1a: membership params
// ---------------------------------------------------------------------------
__global__ void prep_kernel(const float* __restrict__ centers,
                            const float* __restrict__ sigmas) {
    int r = blockIdx.x, d = threadIdx.x;
    float c  = centers[r * D_ + d];
    float sg = sigmas [r * D_ + d];
    float inv = 1.0f / (sg * sg);
    float w = 0.5f * inv;
    float u = c * inv;
    g_wT[d * R_ + r] = w;
    g_uT[d * R_ + r] = u;
    __shared__ float red[128];
    red[d] = w * c * c;
    __syncthreads();
    for (int s = 64; s > 0; s >>= 1) { if (d < s) red[d] += red[d + s]; __syncthreads(); }
    if (d == 0) g_k[r] = red[0];
}

// ---------------------------------------------------------------------------
// Kernel 1b: pack coeffs into mma B-fragment order.
// g_Bf[r][s(16)][jt(8)][lane(32)] = float2{ B[k][j], B[k+4][j] },
//   k = (lane&3)+8s, j = jt*8 + (lane>>2);  B[k][j] = coeffs[r][k][j] (tf32).
// ---------------------------------------------------------------------------
__global__ void __launch_bounds__(256) prep_bf_kernel(const float* __restrict__ coeffs) {
    __shared__ float s[128 * 65];
    int r = blockIdx.x, t = threadIdx.x;
    const float* src = coeffs + (size_t)r * (129 * 64);
    for (int i = t; i < 128 * 64; i += 256) {
        int k = i >> 6, j = i & 63;
        s[k * 65 + j] = tf32r(src[i]);
    }
    __syncthreads();
    float2* dst = (float2*)(g_Bf + (size_t)r * 8192);
    for (int idx = t; idx < 4096; idx += 256) {
        int ss = idx >> 8, jt = (idx >> 5) & 7, l = idx & 31;
        int k = (l & 3) + 8 * ss, j = jt * 8 + (l >> 2);
        dst[idx] = make_float2(s[k * 65 + j], s[(k + 4) * 65 + j]);
    }
}

// Bias fragments per 32-rule split: g_Bbf[sp][s(4)][jt(8)][lane] = float2
//   k = (lane&3)+8s (rule-within-split), j = jt*8+(lane>>2)
__global__ void prep_bbf_kernel(const float* __restrict__ coeffs) {
    int sp = blockIdx.x, t = threadIdx.x;
    float2* dst = (float2*)(g_Bbf + (size_t)sp * 2048);
    for (int idx = t; idx < 1024; idx += 256) {
        int ss = idx >> 8, jt = (idx >> 5) & 7, l = idx & 31;
        int k = (l & 3) + 8 * ss, j = jt * 8 + (l >> 2);
        float v0 = coeffs[(size_t)(sp * 32 + k)     * (129 * 64) + 128 * 64 + j];
        float v1 = coeffs[(size_t)(sp * 32 + k + 4) * (129 * 64) + 128 * 64 + j];
        dst[idx] = make_float2(tf32r(v0), tf32r(v1));
    }
}

// ---------------------------------------------------------------------------
// Kernel 2: strengths + normalization (FFMA2) — unchanged (R1-proven)
// ---------------------------------------------------------------------------
__global__ void __launch_bounds__(256) strengths_kernel(const float* __restrict__ X) {
    extern __shared__ float sm[];
    float* Xs   = sm;                       // [128][32]
    float* E    = Xs + 128 * 32;            // [32][257]
    float* P    = E  + 32 * 257;            // [32][9]
    float* Sinv = P  + 32 * 9;              // [32]

    const int tid = threadIdx.x;
    const int nb  = blockIdx.x * 32;

    for (int idx = tid; idx < 32 * 128; idx += 256) {
        int n = idx >> 7, d = idx & 127;
        Xs[d * 32 + n] = X[(size_t)(nb + n) * D_ + d];
    }
    __syncthreads();

    const int r = tid;
    float kk = g_k[r];
    ull s[16];
    ull init = pack2(-kk, -kk);
    #pragma unroll
    for (int p = 0; p < 16; ++p) s[p] = init;

    for (int d = 0; d < 128; ++d) {
        float w = g_wT[d * R_ + r];
        float u = g_uT[d * R_ + r];
        ull w2 = pack2(-w, -w);
        ull u2 = pack2(u, u);
        const float* xrow = &Xs[d * 32];
        #pragma unroll
        for (int p = 0; p < 16; ++p) {
            ull xp = *(const ull*)&xrow[p * 2];
            ull t  = fma2(w2, xp, u2);
            s[p]   = fma2(t, xp, s[p]);
        }
    }

    float e[32];
    #pragma unroll
    for (int p = 0; p < 16; ++p) {
        float a, b;
        unpack2(s[p], a, b);
        e[2 * p]     = expf(a);
        e[2 * p + 1] = expf(b);
        E[(2 * p)     * 257 + r] = e[2 * p];
        E[(2 * p + 1) * 257 + r] = e[2 * p + 1];
    }
    __syncthreads();

    {
        int n = tid >> 3, c = tid & 7;
        float ps = 0.0f;
        const float* row = &E[n * 257 + c * 32];
        #pragma unroll
        for (int k2 = 0; k2 < 32; ++k2) ps += row[k2];
        P[n * 9 + c] = ps;
    }
    __syncthreads();
    if (tid < 32) {
        float s0 = 0.0f;
        #pragma unroll
        for (int c = 0; c < 8; ++c) s0 += P[tid * 9 + c];
        Sinv[tid] = 1.0f / (s0 + 1e-8f);
    }
    __syncthreads();

    #pragma unroll
    for (int n = 0; n < 32; ++n)
        g_norm[(size_t)(nb + n) * R_ + tid] = e[n] * Sinv[n];
}

// ---------------------------------------------------------------------------
// Kernel 3: main combine with warp-level tf32 mma.sync.
// Grid (32, 8); 128 threads = 4 warps. Warp w owns CTA-local rows [32w, 32w+32)
// = 2 m16 tiles; 8 n8 tiles cover j=0..63. Per rule: A = norm*X generated in
// registers (tf32), B fragments via coalesced LDG.64 from g_Bf (L2).
// Accumulators carry the full sum over rules + bias (4 extra k-steps).
// ---------------------------------------------------------------------------
__global__ void __launch_bounds__(128) main_mma_kernel(const float* __restrict__ X) {
    __shared__ float Ns[128 * 33];

    const int tid  = threadIdx.x;
    const int w    = tid >> 5;
    const int lane = tid & 31;
    const int nb   = blockIdx.x * 128;
    const int sp   = blockIdx.y;
    const int rb   = sp * 32;

    for (int i = tid; i < 128 * 32; i += 128) {
        int n = i >> 5, rl = i & 31;
        Ns[n * 33 + rl] = g_norm[(size_t)(nb + n) * R_ + rb + rl];
    }
    __syncthreads();

    const int gr = lane >> 2;       // 0..7
    const int gc = lane & 3;        // 0..3
    const int row0 = 32 * w + gr;   // CTA-local
    const float* x0 = X + (size_t)(nb + row0) * D_;

    float acc[2][8][4];
    #pragma unroll
    for (int t = 0; t < 2; ++t)
        #pragma unroll
        for (int jt = 0; jt < 8; ++jt)
            #pragma unroll
            for (int q = 0; q < 4; ++q) acc[t][jt][q] = 0.0f;

    for (int rr = 0; rr < 32; ++rr) {
        const int r = rb + rr;
        const float n0 = Ns[(row0)      * 33 + rr];
        const float n1 = Ns[(row0 + 8)  * 33 + rr];
        const float n2 = Ns[(row0 + 16) * 33 + rr];
        const float n3 = Ns[(row0 + 24) * 33 + rr];
        const float2* bp = (const float2*)g_Bf + (size_t)r * 4096 + lane;

        #pragma unroll 4
        for (int s = 0; s < 16; ++s) {
            const int k0 = gc + 8 * s;
            // A fragments (tile0: rows row0,row0+8; tile1: rows +16,+24)
            float a00 = tf32r(x0[k0]            * n0);
            float a01 = tf32r(x0[8 * D_ + k0]   * n1);
            float a02 = tf32r(x0[k0 + 4]        * n0);
            float a03 = tf32r(x0[8 * D_ + k0+4] * n1);
            float a10 = tf32r(x0[16 * D_ + k0]    * n2);
            float a11 = tf32r(x0[24 * D_ + k0]    * n3);
            float a12 = tf32r(x0[16 * D_ + k0 + 4]* n2);
            float a13 = tf32r(x0[24 * D_ + k0 + 4]* n3);

            const float2* bs = bp + s * 256;
            #pragma unroll
            for (int jt = 0; jt < 8; ++jt) {
                float2 b = bs[jt * 32];
                uint32_t b0 = __float_as_uint(b.x), b1 = __float_as_uint(b.y);
                mma_tf32(acc[0][jt], a00, a01, a02, a03, b0, b1);
                mma_tf32(acc[1][jt], a10, a11, a12, a13, b0, b1);
            }
        }
    }

    // ---- bias: 4 extra k-steps, A = norm fragments, B = g_Bbf
    {
        const float2* bb = (const float2*)g_Bbf + (size_t)sp * 1024 + lane;
        #pragma unroll
        for (int s = 0; s < 4; ++s) {
            const int k0 = gc + 8 * s;
            float a00 = tf32r(Ns[(row0)      * 33 + k0]);
            float a01 = tf32r(Ns[(row0 + 8)  * 33 + k0]);
            float a02 = tf32r(Ns[(row0)      * 33 + k0 + 4]);
            float a03 = tf32r(Ns[(row0 + 8)  * 33 + k0 + 4]);
            float a10 = tf32r(Ns[(row0 + 16) * 33 + k0]);
            float a11 = tf32r(Ns[(row0 + 24) * 33 + k0]);
            float a12 = tf32r(Ns[(row0 + 16) * 33 + k0 + 4]);
            float a13 = tf32r(Ns[(row0 + 24) * 33 + k0 + 4]);
            const float2* bs = bb + s * 256;
            #pragma unroll
            for (int jt = 0; jt < 8; ++jt) {
                float2 b = bs[jt * 32];
                uint32_t b0 = __float_as_uint(b.x), b1 = __float_as_uint(b.y);
                mma_tf32(acc[0][jt], a00, a01, a02, a03, b0, b1);
                mma_tf32(acc[1][jt], a10, a11, a12, a13, b0, b1);
            }
        }
    }

    // ---- epilogue: write per-split partial logits
    float* op = g_partial[sp];
    #pragma unroll
    for (int t = 0; t < 2; ++t) {
        const int rA = nb + row0 + 16 * t;
        #pragma unroll
        for (int jt = 0; jt < 8; ++jt) {
            const int c = jt * 8 + 2 * gc;
            *(float2*)(op + (size_t)rA * O_ + c)       = make_float2(acc[t][jt][0], acc[t][jt][1]);
            *(float2*)(op + (size_t)(rA + 8) * O_ + c) = make_float2(acc[t][jt][2], acc[t][jt][3]);
        }
    }
}

// ---------------------------------------------------------------------------
// Kernel 4: reduce partials + softmax
// ---------------------------------------------------------------------------
__global__ void softmax_kernel(float* __restrict__ out) {
    int n = blockIdx.x;
    int j = threadIdx.x;
    float l = 0.0f;
    #pragma unroll
    for (int s = 0; s < 8; ++s) l += g_partial[s][(size_t)n * O_ + j];

    __shared__ float shm[2], shs[2];
    float m = l;
    #pragma unroll
    for (int o = 16; o > 0; o >>= 1) m = fmaxf(m, __shfl_xor_sync(0xffffffff, m, o));
    if ((j & 31) == 0) shm[j >> 5] = m;
    __syncthreads();
    m = fmaxf(shm[0], shm[1]);

    float e = expf(l - m);
    float ssum = e;
    #pragma unroll
    for (int o = 16; o > 0; o >>= 1) ssum += __shfl_xor_sync(0xffffffff, ssum, o);
    if ((j & 31) == 0) shs[j >> 5] = ssum;
    __syncthreads();
    float tot = shs[0] + shs[1];

    out[(size_t)n * O_ + j] = e / tot;
}

// ---------------------------------------------------------------------------
extern "C" void kernel_launch(void* const* d_in, const int* in_sizes, int n_in,
                              void* d_out, int out_size) {
    const float* X       = (const float*)d_in[0];
    const float* centers = (const float*)d_in[1];
    const float* sigmas  = (const float*)d_in[2];
    const float* coeffs  = (const float*)d_in[3];
    float* out = (float*)d_out;

    const int SMEM_S = (128 * 32 + 32 * 257 + 32 * 9 + 32) * (int)sizeof(float);

    cudaFuncSetAttribute(strengths_kernel, cudaFuncAttributeMaxDynamicSharedMemorySize, SMEM_S);

    prep_kernel<<<R_, D_>>>(centers, sigmas);
    prep_bf_kernel<<<R_, 256>>>(coeffs);
    prep_bbf_kernel<<<8, 256>>>(coeffs);
    strengths_kernel<<<N_ / 32, 256, SMEM_S>>>(X);
    main_mma_kernel<<<dim3(N_ / 128, 8), 128>>>(X);
    softmax_kernel<<<N_, O_>>>(out);
}

// round 5
// speedup vs baseline: 3.0620x; 2.5995x over previous
#include <cuda_runtime.h>
#include <cstdint>

#define N_  4096
#define D_  128
#define R_  256
#define O_  64

// ---------------- scratch (__device__ globals) -------------------------------
__device__ float g_w4[D_ * R_];                        // [(d>>2)][r][4] quads
__device__ float g_u4[D_ * R_];
__device__ float g_k[R_];
__device__ float g_norm[(size_t)N_ * R_];              // [n][r]
__device__ float g_Bf[(size_t)R_ * 8192];              // fragment-packed coeffs
__device__ float g_Bbf[8 * 2048];                      // fragment-packed bias / split
__device__ float g_partial[8][(size_t)N_ * O_];        // per-split logits partials

typedef unsigned long long ull;

// ---------------- helpers ----------------------------------------------------
__device__ __forceinline__ ull pack2(float lo, float hi) {
    ull r; asm("mov.b64 %0, {%1, %2};" : "=l"(r) : "f"(lo), "f"(hi)); return r;
}
__device__ __forceinline__ void unpack2(ull v, float& lo, float& hi) {
    asm("mov.b64 {%0, %1}, %2;" : "=f"(lo), "=f"(hi) : "l"(v));
}
__device__ __forceinline__ ull fma2(ull a, ull b, ull c) {
    ull d; asm("fma.rn.f32x2 %0, %1, %2, %3;" : "=l"(d) : "l"(a), "l"(b), "l"(c)); return d;
}
__device__ __forceinline__ float tf32r(float x) {
    uint32_t u; asm("cvt.rna.tf32.f32 %0, %1;" : "=r"(u) : "f"(x));
    return __uint_as_float(u);
}
__device__ __forceinline__ void mma_tf32(float* c,
                                         float a0, float a1, float a2, float a3,
                                         uint32_t b0, uint32_t b1) {
    asm volatile(
        "mma.sync.aligned.m16n8k8.row.col.f32.tf32.tf32.f32 "
        "{%0,%1,%2,%3}, {%4,%5,%6,%7}, {%8,%9}, {%0,%1,%2,%3};"
        : "+f"(c[0]), "+f"(c[1]), "+f"(c[2]), "+f"(c[3])
        : "r"(__float_as_uint(a0)), "r"(__float_as_uint(a1)),
          "r"(__float_as_uint(a2)), "r"(__float_as_uint(a3)),
          "r"(b0), "r"(b1));
}

// ---------------------------------------------------------------------------
// Kernel 1: membership params -> quad layout
// ---------------------------------------------------------------------------
__global__ void prep_kernel(const float* __restrict__ centers,
                            const float* __restrict__ sigmas) {
    int r = blockIdx.x, d = threadIdx.x;
    float c  = centers[r * D_ + d];
    float sg = sigmas [r * D_ + d];
    float inv = 1.0f / (sg * sg);
    float w = 0.5f * inv;
    float u = c * inv;
    int q = (d >> 2) * (R_ * 4) + r * 4 + (d & 3);
    g_w4[q] = w;
    g_u4[q] = u;
    __shared__ float red[128];
    red[d] = w * c * c;
    __syncthreads();
    for (int s = 64; s > 0; s >>= 1) { if (d < s) red[d] += red[d + s]; __syncthreads(); }
    if (d == 0) g_k[r] = red[0];
}

// ---------------------------------------------------------------------------
// Kernel 2: strengths + normalization. 128 blocks x 256 thr, 32 rows/block.
// Thread = rule. Xs stride 34 (EVEN -> 8B-aligned ull loads; 2-way store
// conflicts max; reads are uniform broadcast).
// ---------------------------------------------------------------------------
#define XSTR 34
__global__ void __launch_bounds__(256) strengths_kernel(const float* __restrict__ X) {
    __shared__ float Xs[128 * XSTR];        // ~17 KB
    __shared__ float Wsum[8][32];
    __shared__ float Sinv[32];

    const int tid = threadIdx.x;            // rule index
    const int nb  = blockIdx.x * 32;
    const int lane = tid & 31, wp = tid >> 5;

    for (int idx = tid; idx < 32 * 128; idx += 256) {
        int n = idx >> 7, d = idx & 127;
        Xs[d * XSTR + n] = X[(size_t)(nb + n) * D_ + d];
    }
    __syncthreads();

    const int r = tid;
    float kk = g_k[r];
    ull s[16];
    ull init = pack2(-kk, -kk);
    #pragma unroll
    for (int p = 0; p < 16; ++p) s[p] = init;

    #pragma unroll 2
    for (int c = 0; c < 32; ++c) {          // 4 dims per chunk
        float4 w4 = *(const float4*)&g_w4[(c * R_ + r) * 4];
        float4 u4 = *(const float4*)&g_u4[(c * R_ + r) * 4];
        const float wv[4] = {w4.x, w4.y, w4.z, w4.w};
        const float uv[4] = {u4.x, u4.y, u4.z, u4.w};
        #pragma unroll
        for (int dd = 0; dd < 4; ++dd) {
            ull w2 = pack2(-wv[dd], -wv[dd]);
            ull u2 = pack2(uv[dd], uv[dd]);
            const float* xrow = &Xs[(c * 4 + dd) * XSTR];
            #pragma unroll
            for (int p = 0; p < 16; ++p) {
                ull xp = *(const ull*)&xrow[p * 2];
                ull t  = fma2(w2, xp, u2);
                s[p]   = fma2(t, xp, s[p]);
            }
        }
    }

    float e[32];
    #pragma unroll
    for (int p = 0; p < 16; ++p) {
        float a, b;
        unpack2(s[p], a, b);
        e[2 * p]     = expf(a);
        e[2 * p + 1] = expf(b);
    }

    // row sums across 256 rules: warp shuffle then cross-warp
    #pragma unroll
    for (int n = 0; n < 32; ++n) {
        float v = e[n];
        #pragma unroll
        for (int o = 16; o > 0; o >>= 1) v += __shfl_xor_sync(0xffffffff, v, o);
        if (lane == 0) Wsum[wp][n] = v;
    }
    __syncthreads();
    if (tid < 32) {
        float s0 = 0.0f;
        #pragma unroll
        for (int w = 0; w < 8; ++w) s0 += Wsum[w][tid];
        Sinv[tid] = 1.0f / (s0 + 1e-8f);
    }
    __syncthreads();

    #pragma unroll
    for (int n = 0; n < 32; ++n)
        g_norm[(size_t)(nb + n) * R_ + r] = e[n] * Sinv[n];
}

// ---------------------------------------------------------------------------
// Kernel 3 (prep): pack coeffs + bias into mma B-fragment order.
// g_Bf[r][s(16)][jt(8)][lane] = float2{B[k][j], B[k+4][j]},
//   k=(lane&3)+8s, j=jt*8+(lane>>2). Blocks r<8 also pack bias for split r.
// ---------------------------------------------------------------------------
__global__ void __launch_bounds__(256) prep_bf_kernel(const float* __restrict__ coeffs) {
    __shared__ float s[128 * 65];
    int r = blockIdx.x, t = threadIdx.x;
    const float* src = coeffs + (size_t)r * (129 * 64);
    for (int i = t; i < 128 * 64; i += 256) {
        int k = i >> 6, j = i & 63;
        s[k * 65 + j] = tf32r(src[i]);
    }
    __syncthreads();
    float2* dst = (float2*)(g_Bf + (size_t)r * 8192);
    for (int idx = t; idx < 4096; idx += 256) {
        int ss = idx >> 8, jt = (idx >> 5) & 7, l = idx & 31;
        int k = (l & 3) + 8 * ss, j = jt * 8 + (l >> 2);
        dst[idx] = make_float2(s[k * 65 + j], s[(k + 4) * 65 + j]);
    }
    if (r < 8) {
        float2* bdst = (float2*)(g_Bbf + (size_t)r * 2048);
        for (int idx = t; idx < 1024; idx += 256) {
            int ss = idx >> 8, jt = (idx >> 5) & 7, l = idx & 31;
            int k = (l & 3) + 8 * ss, j = jt * 8 + (l >> 2);
            float v0 = coeffs[(size_t)(r * 32 + k)     * (129 * 64) + 128 * 64 + j];
            float v1 = coeffs[(size_t)(r * 32 + k + 4) * (129 * 64) + 128 * 64 + j];
            bdst[idx] = make_float2(tf32r(v0), tf32r(v1));
        }
    }
}

// ---------------------------------------------------------------------------
// Kernel 4: main combine. Grid (64, 8), 128 thr (4 warps), 64 rows/CTA.
// Warp = one m16 tile (16 rows) x 8 n8 tiles. X fragments register-resident.
// ---------------------------------------------------------------------------
__global__ void __launch_bounds__(128, 3) main_mma_kernel(const float* __restrict__ X) {
    __shared__ float Ns[64 * 33];

    const int tid  = threadIdx.x;
    const int w    = tid >> 5;
    const int lane = tid & 31;
    const int gr   = lane >> 2;
    const int gc   = lane & 3;
    const int nb   = blockIdx.x * 64;
    const int sp   = blockIdx.y;
    const int rb   = sp * 32;

    for (int i = tid; i < 64 * 32; i += 128) {
        int n = i >> 5, rl = i & 31;
        Ns[n * 33 + rl] = g_norm[(size_t)(nb + n) * R_ + rb + rl];
    }

    const int rA = 16 * w + gr;          // CTA-local rows of this thread
    const int rB = rA + 8;
    // X fragments, register resident: xa[t] = X[rA][gc+4t]
    float xa[32], xb[32];
    {
        const float* pa = X + (size_t)(nb + rA) * D_ + gc;
        const float* pb = X + (size_t)(nb + rB) * D_ + gc;
        #pragma unroll
        for (int t = 0; t < 32; ++t) { xa[t] = pa[4 * t]; xb[t] = pb[4 * t]; }
    }
    __syncthreads();

    float acc[8][4];
    #pragma unroll
    for (int jt = 0; jt < 8; ++jt)
        #pragma unroll
        for (int q = 0; q < 4; ++q) acc[jt][q] = 0.0f;

    for (int rr = 0; rr < 32; ++rr) {
        const float nA = Ns[rA * 33 + rr];
        const float nB = Ns[rB * 33 + rr];
        const float2* bp = (const float2*)g_Bf + (size_t)(rb + rr) * 4096 + lane;

        #pragma unroll
        for (int s = 0; s < 16; ++s) {
            float a0 = tf32r(xa[2 * s]     * nA);
            float a1 = tf32r(xb[2 * s]     * nB);
            float a2 = tf32r(xa[2 * s + 1] * nA);
            float a3 = tf32r(xb[2 * s + 1] * nB);
            const float2* bs = bp + s * 256;
            #pragma unroll
            for (int jt = 0; jt < 8; ++jt) {
                float2 b = bs[jt * 32];
                mma_tf32(acc[jt], a0, a1, a2, a3,
                         __float_as_uint(b.x), __float_as_uint(b.y));
            }
        }
    }

    // bias: 4 extra k-steps, A = norm fragments
    {
        const float2* bb = (const float2*)g_Bbf + (size_t)sp * 1024 + lane;
        #pragma unroll
        for (int s = 0; s < 4; ++s) {
            const int k0 = gc + 8 * s;
            float a0 = tf32r(Ns[rA * 33 + k0]);
            float a1 = tf32r(Ns[rB * 33 + k0]);
            float a2 = tf32r(Ns[rA * 33 + k0 + 4]);
            float a3 = tf32r(Ns[rB * 33 + k0 + 4]);
            const float2* bs = bb + s * 256;
            #pragma unroll
            for (int jt = 0; jt < 8; ++jt) {
                float2 b = bs[jt * 32];
                mma_tf32(acc[jt], a0, a1, a2, a3,
                         __float_as_uint(b.x), __float_as_uint(b.y));
            }
        }
    }

    float* op = g_partial[sp];
    #pragma unroll
    for (int jt = 0; jt < 8; ++jt) {
        const int c = jt * 8 + 2 * gc;
        *(float2*)(op + (size_t)(nb + rA) * O_ + c) = make_float2(acc[jt][0], acc[jt][1]);
        *(float2*)(op + (size_t)(nb + rB) * O_ + c) = make_float2(acc[jt][2], acc[jt][3]);
    }
}

// ---------------------------------------------------------------------------
// Kernel 5: reduce partials + softmax
// ---------------------------------------------------------------------------
__global__ void softmax_kernel(float* __restrict__ out) {
    int n = blockIdx.x;
    int j = threadIdx.x;
    float l = 0.0f;
    #pragma unroll
    for (int s = 0; s < 8; ++s) l += g_partial[s][(size_t)n * O_ + j];

    __shared__ float shm[2], shs[2];
    float m = l;
    #pragma unroll
    for (int o = 16; o > 0; o >>= 1) m = fmaxf(m, __shfl_xor_sync(0xffffffff, m, o));
    if ((j & 31) == 0) shm[j >> 5] = m;
    __syncthreads();
    m = fmaxf(shm[0], shm[1]);

    float e = expf(l - m);
    float ssum = e;
    #pragma unroll
    for (int o = 16; o > 0; o >>= 1) ssum += __shfl_xor_sync(0xffffffff, ssum, o);
    if ((j & 31) == 0) shs[j >> 5] = ssum;
    __syncthreads();
    float tot = shs[0] + shs[1];

    out[(size_t)n * O_ + j] = e / tot;
}

// ---------------------------------------------------------------------------
// Launch order puts main_mma_kernel at index 3 (the launch ncu captures).
// ---------------------------------------------------------------------------
extern "C" void kernel_launch(void* const* d_in, const int* in_sizes, int n_in,
                              void* d_out, int out_size) {
    const float* X       = (const float*)d_in[0];
    const float* centers = (const float*)d_in[1];
    const float* sigmas  = (const float*)d_in[2];
    const float* coeffs  = (const float*)d_in[3];
    float* out = (float*)d_out;

    prep_kernel<<<R_, D_>>>(centers, sigmas);                 // 0
    strengths_kernel<<<N_ / 32, 256>>>(X);                    // 1
    prep_bf_kernel<<<R_, 256>>>(coeffs);                      // 2
    main_mma_kernel<<<dim3(N_ / 64, 8), 128>>>(X);            // 3  <- ncu capture slot
    softmax_kernel<<<N_, O_>>>(out);                          // 4
}

// round 6
// speedup vs baseline: 6.6722x; 2.1791x over previous
#include <cuda_runtime.h>
#include <cstdint>

#define N_  4096
#define D_  128
#define R_  256
#define O_  64

typedef unsigned long long ull;

// ---------------- scratch (__device__ globals) -------------------------------
__device__ float g_w4[D_ * R_];                        // [(d>>2)][r][4] quads
__device__ float g_u4[D_ * R_];
__device__ float g_k[R_];
__device__ float g_norm[(size_t)N_ * R_];              // [n][r]
__device__ __align__(16) ull g_Bh[(size_t)R_ * 2048];  // bf16 B fragments [r][kk8][jt8][lane32] (4 MB)
__device__ __align__(16) ull g_Bbh[8 * 512];           // bf16 bias fragments [sp][kk2][jt8][lane32]
__device__ float g_partial[8][(size_t)N_ * O_];        // per-split logits partials

// ---------------- helpers ----------------------------------------------------
__device__ __forceinline__ ull pack2(float lo, float hi) {
    ull r; asm("mov.b64 %0, {%1, %2};" : "=l"(r) : "f"(lo), "f"(hi)); return r;
}
__device__ __forceinline__ void unpack2(ull v, float& lo, float& hi) {
    asm("mov.b64 {%0, %1}, %2;" : "=f"(lo), "=f"(hi) : "l"(v));
}
__device__ __forceinline__ ull fma2(ull a, ull b, ull c) {
    ull d; asm("fma.rn.f32x2 %0, %1, %2, %3;" : "=l"(d) : "l"(a), "l"(b), "l"(c)); return d;
}
// bf16x2 pack: lo = a, hi = b
__device__ __forceinline__ uint32_t bf2(float a, float b) {
    uint32_t r; asm("cvt.rn.bf16x2.f32 %0, %1, %2;" : "=r"(r) : "f"(b), "f"(a)); return r;
}
__device__ __forceinline__ uint32_t hmul2(uint32_t a, uint32_t b) {
    uint32_t r; asm("mul.bf16x2 %0, %1, %2;" : "=r"(r) : "r"(a), "r"(b)); return r;
}
__device__ __forceinline__ void u64lohi(ull v, uint32_t& lo, uint32_t& hi) {
    asm("mov.b64 {%0, %1}, %2;" : "=r"(lo), "=r"(hi) : "l"(v));
}
__device__ __forceinline__ uint32_t smem_u32(const void* p) {
    uint32_t a;
    asm("{ .reg .u64 t; cvta.to.shared.u64 t, %1; cvt.u32.u64 %0, t; }" : "=r"(a) : "l"(p));
    return a;
}
// m16n8k16 bf16 MMA
__device__ __forceinline__ void mma_bf16(float* c,
                                         uint32_t a0, uint32_t a1, uint32_t a2, uint32_t a3,
                                         uint32_t b0, uint32_t b1) {
    asm volatile(
        "mma.sync.aligned.m16n8k16.row.col.f32.bf16.bf16.f32 "
        "{%0,%1,%2,%3}, {%4,%5,%6,%7}, {%8,%9}, {%0,%1,%2,%3};"
        : "+f"(c[0]), "+f"(c[1]), "+f"(c[2]), "+f"(c[3])
        : "r"(a0), "r"(a1), "r"(a2), "r"(a3), "r"(b0), "r"(b1));
}

// ---------------------------------------------------------------------------
// Kernel 1: membership params -> quad layout
// ---------------------------------------------------------------------------
__global__ void prep_kernel(const float* __restrict__ centers,
                            const float* __restrict__ sigmas) {
    int r = blockIdx.x, d = threadIdx.x;
    float c  = centers[r * D_ + d];
    float sg = sigmas [r * D_ + d];
    float inv = 1.0f / (sg * sg);
    float w = 0.5f * inv;
    float u = c * inv;
    int q = (d >> 2) * (R_ * 4) + r * 4 + (d & 3);
    g_w4[q] = w;
    g_u4[q] = u;
    __shared__ float red[128];
    red[d] = w * c * c;
    __syncthreads();
    for (int s = 64; s > 0; s >>= 1) { if (d < s) red[d] += red[d + s]; __syncthreads(); }
    if (d == 0) g_k[r] = red[0];
}

// ---------------------------------------------------------------------------
// Kernel 2: strengths + normalization. 512 blocks x 256 thr, 8 rows/block.
// Thread = rule.
// ---------------------------------------------------------------------------
#define XSTR 10
__global__ void __launch_bounds__(256) strengths_kernel(const float* __restrict__ X) {
    __shared__ float Xs[128 * XSTR];        // [d][n], 5 KB
    __shared__ float Wsum[8][8];
    __shared__ float Sinv[8];

    const int tid = threadIdx.x;            // rule index
    const int nb  = blockIdx.x * 8;
    const int lane = tid & 31, wp = tid >> 5;

    for (int idx = tid; idx < 8 * 128; idx += 256) {
        int n = idx >> 7, d = idx & 127;
        Xs[d * XSTR + n] = X[(size_t)(nb + n) * D_ + d];
    }
    __syncthreads();

    const int r = tid;
    float kk = g_k[r];
    ull s[4];
    ull init = pack2(-kk, -kk);
    #pragma unroll
    for (int p = 0; p < 4; ++p) s[p] = init;

    #pragma unroll 4
    for (int c = 0; c < 32; ++c) {          // 4 dims per chunk
        float4 w4 = *(const float4*)&g_w4[(c * R_ + r) * 4];
        float4 u4 = *(const float4*)&g_u4[(c * R_ + r) * 4];
        const float wv[4] = {w4.x, w4.y, w4.z, w4.w};
        const float uv[4] = {u4.x, u4.y, u4.z, u4.w};
        #pragma unroll
        for (int dd = 0; dd < 4; ++dd) {
            ull w2 = pack2(-wv[dd], -wv[dd]);
            ull u2 = pack2(uv[dd], uv[dd]);
            const float* xrow = &Xs[(c * 4 + dd) * XSTR];
            #pragma unroll
            for (int p = 0; p < 4; ++p) {
                ull xp = *(const ull*)&xrow[p * 2];
                ull t  = fma2(w2, xp, u2);
                s[p]   = fma2(t, xp, s[p]);
            }
        }
    }

    float e[8];
    #pragma unroll
    for (int p = 0; p < 4; ++p) {
        float a, b;
        unpack2(s[p], a, b);
        e[2 * p]     = expf(a);
        e[2 * p + 1] = expf(b);
    }

    #pragma unroll
    for (int n = 0; n < 8; ++n) {
        float v = e[n];
        #pragma unroll
        for (int o = 16; o > 0; o >>= 1) v += __shfl_xor_sync(0xffffffff, v, o);
        if (lane == 0) Wsum[wp][n] = v;
    }
    __syncthreads();
    if (tid < 8) {
        float s0 = 0.0f;
        #pragma unroll
        for (int w = 0; w < 8; ++w) s0 += Wsum[w][tid];
        Sinv[tid] = 1.0f / (s0 + 1e-8f);
    }
    __syncthreads();

    #pragma unroll
    for (int n = 0; n < 8; ++n)
        g_norm[(size_t)(nb + n) * R_ + r] = e[n] * Sinv[n];
}

// ---------------------------------------------------------------------------
// Kernel 3 (prep): pack coeffs + bias into bf16 m16n8k16 B-fragment order.
// g_Bh[r][kk][jt][lane] = ull{ b0=bf16x2{B[K0][j],B[K0+1][j]},
//                              b1=bf16x2{B[K0+8][j],B[K0+9][j]} },
//   K0 = kk*16 + (lane&3)*2, j = jt*8 + (lane>>2).
// Blocks r<8 also pack split-r bias the same way over the 32-rule k-dim.
// ---------------------------------------------------------------------------
__global__ void __launch_bounds__(256) prep_bh_kernel(const float* __restrict__ coeffs) {
    int r = blockIdx.x, t = threadIdx.x;
    const float* src = coeffs + (size_t)r * (129 * 64);
    ull* dst = g_Bh + (size_t)r * 2048;
    for (int idx = t; idx < 2048; idx += 256) {
        int kk = idx >> 8, jt = (idx >> 5) & 7, l = idx & 31;
        int K0 = kk * 16 + (l & 3) * 2, j = jt * 8 + (l >> 2);
        uint32_t b0 = bf2(src[K0 * 64 + j],       src[(K0 + 1) * 64 + j]);
        uint32_t b1 = bf2(src[(K0 + 8) * 64 + j], src[(K0 + 9) * 64 + j]);
        ull v; asm("mov.b64 %0, {%1, %2};" : "=l"(v) : "r"(b0), "r"(b1));
        dst[idx] = v;
    }
    if (r < 8) {
        ull* bdst = g_Bbh + (size_t)r * 512;
        for (int idx = t; idx < 512; idx += 256) {
            int kk = idx >> 8, jt = (idx >> 5) & 7, l = idx & 31;
            int K0 = kk * 16 + (l & 3) * 2, j = jt * 8 + (l >> 2);
            #define BIAS(k) coeffs[(size_t)(r * 32 + (k)) * (129 * 64) + 128 * 64 + j]
            uint32_t b0 = bf2(BIAS(K0),     BIAS(K0 + 1));
            uint32_t b1 = bf2(BIAS(K0 + 8), BIAS(K0 + 9));
            #undef BIAS
            ull v; asm("mov.b64 %0, {%1, %2};" : "=l"(v) : "r"(b0), "r"(b1));
            bdst[idx] = v;
        }
    }
}

// ---------------------------------------------------------------------------
// Kernel 4: main combine, bf16 m16n8k16. Grid (64, 8), 128 thr (4 warps).
// Warp = m16 tile x 8 n8 tiles. X bf16x2 register-resident; B double-buffered
// through smem via cp.async (prefetch next rule during compute).
// ---------------------------------------------------------------------------
__global__ void __launch_bounds__(128, 4) main_mma_kernel(const float* __restrict__ X) {
    __shared__ __align__(16) ull Bbuf[2][2048];       // 32 KB
    __shared__ float Ns[64 * 33];                      // 8.4 KB

    const int tid  = threadIdx.x;
    const int w    = tid >> 5;
    const int lane = tid & 31;
    const int gr   = lane >> 2;
    const int gc   = lane & 3;
    const int nb   = blockIdx.x * 64;
    const int sp   = blockIdx.y;
    const int rb   = sp * 32;

    for (int i = tid; i < 64 * 32; i += 128) {
        int n = i >> 5, rl = i & 31;
        Ns[n * 33 + rl] = g_norm[(size_t)(nb + n) * R_ + rb + rl];
    }

    const int rA = 16 * w + gr;
    const int rB = rA + 8;
    // X fragments as bf16x2: x?0[kk] = {X[row][16kk+2gc], +1}, x?1[kk] = {+8, +9}
    uint32_t xA0[8], xA1[8], xB0[8], xB1[8];
    {
        const float* pa = X + (size_t)(nb + rA) * D_ + 2 * gc;
        const float* pb = X + (size_t)(nb + rB) * D_ + 2 * gc;
        #pragma unroll
        for (int kk = 0; kk < 8; ++kk) {
            float2 v;
            v = *(const float2*)(pa + 16 * kk);     xA0[kk] = bf2(v.x, v.y);
            v = *(const float2*)(pa + 16 * kk + 8); xA1[kk] = bf2(v.x, v.y);
            v = *(const float2*)(pb + 16 * kk);     xB0[kk] = bf2(v.x, v.y);
            v = *(const float2*)(pb + 16 * kk + 8); xB1[kk] = bf2(v.x, v.y);
        }
    }

    const uint32_t bsm = smem_u32(&Bbuf[0][0]);

    // stage rule 0
    {
        const ull* src = g_Bh + (size_t)rb * 2048;
        #pragma unroll
        for (int q = 0; q < 8; ++q) {
            int c16 = tid + q * 128;
            asm volatile("cp.async.cg.shared.global [%0], [%1], 16;"
                         :: "r"(bsm + c16 * 16), "l"(src + c16 * 2) : "memory");
        }
        asm volatile("cp.async.commit_group;" ::: "memory");
    }

    float acc[8][4];
    #pragma unroll
    for (int jt = 0; jt < 8; ++jt)
        #pragma unroll
        for (int q = 0; q < 4; ++q) acc[jt][q] = 0.0f;

    __syncthreads();   // Ns ready (also covers first-buffer WAR)

    for (int rr = 0; rr < 32; ++rr) {
        if (rr + 1 < 32) {   // prefetch next rule
            const ull* src = g_Bh + (size_t)(rb + rr + 1) * 2048;
            const uint32_t dst = bsm + ((rr + 1) & 1) * 16384;
            #pragma unroll
            for (int q = 0; q < 8; ++q) {
                int c16 = tid + q * 128;
                asm volatile("cp.async.cg.shared.global [%0], [%1], 16;"
                             :: "r"(dst + c16 * 16), "l"(src + c16 * 2) : "memory");
            }
            asm volatile("cp.async.commit_group;" ::: "memory");
            asm volatile("cp.async.wait_group 1;" ::: "memory");
        } else {
            asm volatile("cp.async.wait_group 0;" ::: "memory");
        }
        __syncthreads();    // rule rr's buffer complete for all threads

        const float nA = Ns[rA * 33 + rr];
        const float nB = Ns[rB * 33 + rr];
        const uint32_t n2A = bf2(nA, nA);
        const uint32_t n2B = bf2(nB, nB);
        const ull* bb = &Bbuf[rr & 1][lane];

        #pragma unroll
        for (int kk = 0; kk < 8; ++kk) {
            uint32_t a0 = hmul2(xA0[kk], n2A);
            uint32_t a1 = hmul2(xB0[kk], n2B);
            uint32_t a2 = hmul2(xA1[kk], n2A);
            uint32_t a3 = hmul2(xB1[kk], n2B);
            #pragma unroll
            for (int jt = 0; jt < 8; ++jt) {
                ull bv = bb[(kk * 8 + jt) * 32];
                uint32_t b0, b1;
                u64lohi(bv, b0, b1);
                mma_bf16(acc[jt], a0, a1, a2, a3, b0, b1);
            }
        }
        __syncthreads();    // all warps done reading before buffer reuse
    }

    // ---- bias: 2 extra k16 steps, A = norm fragments, B from g_Bbh (L2)
    {
        const ull* bb = g_Bbh + (size_t)sp * 512 + lane;
        #pragma unroll
        for (int kk = 0; kk < 2; ++kk) {
            const int K0 = kk * 16 + 2 * gc;
            uint32_t a0 = bf2(Ns[rA * 33 + K0],     Ns[rA * 33 + K0 + 1]);
            uint32_t a1 = bf2(Ns[rB * 33 + K0],     Ns[rB * 33 + K0 + 1]);
            uint32_t a2 = bf2(Ns[rA * 33 + K0 + 8], Ns[rA * 33 + K0 + 9]);
            uint32_t a3 = bf2(Ns[rB * 33 + K0 + 8], Ns[rB * 33 + K0 + 9]);
            #pragma unroll
            for (int jt = 0; jt < 8; ++jt) {
                ull bv = bb[(kk * 8 + jt) * 32];
                uint32_t b0, b1;
                u64lohi(bv, b0, b1);
                mma_bf16(acc[jt], a0, a1, a2, a3, b0, b1);
            }
        }
    }

    float* op = g_partial[sp];
    #pragma unroll
    for (int jt = 0; jt < 8; ++jt) {
        const int c = jt * 8 + 2 * gc;
        *(float2*)(op + (size_t)(nb + rA) * O_ + c) = make_float2(acc[jt][0], acc[jt][1]);
        *(float2*)(op + (size_t)(nb + rB) * O_ + c) = make_float2(acc[jt][2], acc[jt][3]);
    }
}

// ---------------------------------------------------------------------------
// Kernel 5: reduce partials + softmax
// ---------------------------------------------------------------------------
__global__ void softmax_kernel(float* __restrict__ out) {
    int n = blockIdx.x;
    int j = threadIdx.x;
    float l = 0.0f;
    #pragma unroll
    for (int s = 0; s < 8; ++s) l += g_partial[s][(size_t)n * O_ + j];

    __shared__ float shm[2], shs[2];
    float m = l;
    #pragma unroll
    for (int o = 16; o > 0; o >>= 1) m = fmaxf(m, __shfl_xor_sync(0xffffffff, m, o));
    if ((j & 31) == 0) shm[j >> 5] = m;
    __syncthreads();
    m = fmaxf(shm[0], shm[1]);

    float e = expf(l - m);
    float ssum = e;
    #pragma unroll
    for (int o = 16; o > 0; o >>= 1) ssum += __shfl_xor_sync(0xffffffff, ssum, o);
    if ((j & 31) == 0) shs[j >> 5] = ssum;
    __syncthreads();
    float tot = shs[0] + shs[1];

    out[(size_t)n * O_ + j] = e / tot;
}

// ---------------------------------------------------------------------------
extern "C" void kernel_launch(void* const* d_in, const int* in_sizes, int n_in,
                              void* d_out, int out_size) {
    const float* X       = (const float*)d_in[0];
    const float* centers = (const float*)d_in[1];
    const float* sigmas  = (const float*)d_in[2];
    const float* coeffs  = (const float*)d_in[3];
    float* out = (float*)d_out;

    prep_kernel<<<R_, D_>>>(centers, sigmas);                 // 0
    strengths_kernel<<<N_ / 8, 256>>>(X);                     // 1
    prep_bh_kernel<<<R_, 256>>>(coeffs);                      // 2
    main_mma_kernel<<<dim3(N_ / 64, 8), 128>>>(X);            // 3  <- ncu capture slot
    softmax_kernel<<<N_, O_>>>(out);                          // 4
}

// round 7
// speedup vs baseline: 6.8108x; 1.0208x over previous
#include <cuda_runtime.h>
#include <cstdint>

#define N_  4096
#define D_  128
#define R_  256
#define O_  64

typedef unsigned long long ull;

// ---------------- scratch (__device__ globals) -------------------------------
__device__ float g_w4[D_ * R_];
__device__ float g_u4[D_ * R_];
__device__ float g_k[R_];
__device__ float g_norm[(size_t)N_ * R_];              // [n][r]
__device__ __align__(16) ull g_Bh[(size_t)R_ * 2048];  // bf16 B fragments (4 MB)
__device__ __align__(16) ull g_Bbh[8 * 512];           // bf16 bias fragments
__device__ float g_partial[8][(size_t)N_ * O_];

// ---------------- helpers ----------------------------------------------------
__device__ __forceinline__ ull pack2(float lo, float hi) {
    ull r; asm("mov.b64 %0, {%1, %2};" : "=l"(r) : "f"(lo), "f"(hi)); return r;
}
__device__ __forceinline__ void unpack2(ull v, float& lo, float& hi) {
    asm("mov.b64 {%0, %1}, %2;" : "=f"(lo), "=f"(hi) : "l"(v));
}
__device__ __forceinline__ ull fma2(ull a, ull b, ull c) {
    ull d; asm("fma.rn.f32x2 %0, %1, %2, %3;" : "=l"(d) : "l"(a), "l"(b), "l"(c)); return d;
}
__device__ __forceinline__ uint32_t bf2(float a, float b) {
    uint32_t r; asm("cvt.rn.bf16x2.f32 %0, %1, %2;" : "=r"(r) : "f"(b), "f"(a)); return r;
}
__device__ __forceinline__ uint32_t hmul2(uint32_t a, uint32_t b) {
    uint32_t r; asm("mul.bf16x2 %0, %1, %2;" : "=r"(r) : "r"(a), "r"(b)); return r;
}
__device__ __forceinline__ void u64lohi(ull v, uint32_t& lo, uint32_t& hi) {
    asm("mov.b64 {%0, %1}, %2;" : "=r"(lo), "=r"(hi) : "l"(v));
}
__device__ __forceinline__ uint32_t smem_u32(const void* p) {
    uint32_t a;
    asm("{ .reg .u64 t; cvta.to.shared.u64 t, %1; cvt.u32.u64 %0, t; }" : "=r"(a) : "l"(p));
    return a;
}
__device__ __forceinline__ void mma_bf16(float* c,
                                         uint32_t a0, uint32_t a1, uint32_t a2, uint32_t a3,
                                         uint32_t b0, uint32_t b1) {
    asm volatile(
        "mma.sync.aligned.m16n8k16.row.col.f32.bf16.bf16.f32 "
        "{%0,%1,%2,%3}, {%4,%5,%6,%7}, {%8,%9}, {%0,%1,%2,%3};"
        : "+f"(c[0]), "+f"(c[1]), "+f"(c[2]), "+f"(c[3])
        : "r"(a0), "r"(a1), "r"(a2), "r"(a3), "r"(b0), "r"(b1));
}

// ---------------------------------------------------------------------------
// Kernel 1: membership params -> quad layout
// ---------------------------------------------------------------------------
__global__ void prep_kernel(const float* __restrict__ centers,
                            const float* __restrict__ sigmas) {
    int r = blockIdx.x, d = threadIdx.x;
    float c  = centers[r * D_ + d];
    float sg = sigmas [r * D_ + d];
    float inv = 1.0f / (sg * sg);
    float w = 0.5f * inv;
    float u = c * inv;
    int q = (d >> 2) * (R_ * 4) + r * 4 + (d & 3);
    g_w4[q] = w;
    g_u4[q] = u;
    __shared__ float red[128];
    red[d] = w * c * c;
    __syncthreads();
    for (int s = 64; s > 0; s >>= 1) { if (d < s) red[d] += red[d + s]; __syncthreads(); }
    if (d == 0) g_k[r] = red[0];
}

// ---------------------------------------------------------------------------
// Kernel 2: strengths + normalization. 512 blocks x 256 thr, 8 rows/block.
// ---------------------------------------------------------------------------
#define XSTR 10
__global__ void __launch_bounds__(256) strengths_kernel(const float* __restrict__ X) {
    __shared__ float Xs[128 * XSTR];
    __shared__ float Wsum[8][8];
    __shared__ float Sinv[8];

    const int tid = threadIdx.x;
    const int nb  = blockIdx.x * 8;
    const int lane = tid & 31, wp = tid >> 5;

    for (int idx = tid; idx < 8 * 128; idx += 256) {
        int n = idx >> 7, d = idx & 127;
        Xs[d * XSTR + n] = X[(size_t)(nb + n) * D_ + d];
    }
    __syncthreads();

    const int r = tid;
    float kk = g_k[r];
    ull s[4];
    ull init = pack2(-kk, -kk);
    #pragma unroll
    for (int p = 0; p < 4; ++p) s[p] = init;

    #pragma unroll 4
    for (int c = 0; c < 32; ++c) {
        float4 w4 = *(const float4*)&g_w4[(c * R_ + r) * 4];
        float4 u4 = *(const float4*)&g_u4[(c * R_ + r) * 4];
        const float wv[4] = {w4.x, w4.y, w4.z, w4.w};
        const float uv[4] = {u4.x, u4.y, u4.z, u4.w};
        #pragma unroll
        for (int dd = 0; dd < 4; ++dd) {
            ull w2 = pack2(-wv[dd], -wv[dd]);
            ull u2 = pack2(uv[dd], uv[dd]);
            const float* xrow = &Xs[(c * 4 + dd) * XSTR];
            #pragma unroll
            for (int p = 0; p < 4; ++p) {
                ull xp = *(const ull*)&xrow[p * 2];
                ull t  = fma2(w2, xp, u2);
                s[p]   = fma2(t, xp, s[p]);
            }
        }
    }

    float e[8];
    #pragma unroll
    for (int p = 0; p < 4; ++p) {
        float a, b;
        unpack2(s[p], a, b);
        e[2 * p]     = expf(a);
        e[2 * p + 1] = expf(b);
    }

    #pragma unroll
    for (int n = 0; n < 8; ++n) {
        float v = e[n];
        #pragma unroll
        for (int o = 16; o > 0; o >>= 1) v += __shfl_xor_sync(0xffffffff, v, o);
        if (lane == 0) Wsum[wp][n] = v;
    }
    __syncthreads();
    if (tid < 8) {
        float s0 = 0.0f;
        #pragma unroll
        for (int w = 0; w < 8; ++w) s0 += Wsum[w][tid];
        Sinv[tid] = 1.0f / (s0 + 1e-8f);
    }
    __syncthreads();

    #pragma unroll
    for (int n = 0; n < 8; ++n)
        g_norm[(size_t)(nb + n) * R_ + r] = e[n] * Sinv[n];
}

// ---------------------------------------------------------------------------
// Kernel 3 (prep): pack coeffs + bias into bf16 m16n8k16 B-fragment order.
// ---------------------------------------------------------------------------
__global__ void __launch_bounds__(256) prep_bh_kernel(const float* __restrict__ coeffs) {
    int r = blockIdx.x, t = threadIdx.x;
    const float* src = coeffs + (size_t)r * (129 * 64);
    ull* dst = g_Bh + (size_t)r * 2048;
    for (int idx = t; idx < 2048; idx += 256) {
        int kk = idx >> 8, jt = (idx >> 5) & 7, l = idx & 31;
        int K0 = kk * 16 + (l & 3) * 2, j = jt * 8 + (l >> 2);
        uint32_t b0 = bf2(src[K0 * 64 + j],       src[(K0 + 1) * 64 + j]);
        uint32_t b1 = bf2(src[(K0 + 8) * 64 + j], src[(K0 + 9) * 64 + j]);
        ull v; asm("mov.b64 %0, {%1, %2};" : "=l"(v) : "r"(b0), "r"(b1));
        dst[idx] = v;
    }
    if (r < 8) {
        ull* bdst = g_Bbh + (size_t)r * 512;
        for (int idx = t; idx < 512; idx += 256) {
            int kk = idx >> 8, jt = (idx >> 5) & 7, l = idx & 31;
            int K0 = kk * 16 + (l & 3) * 2, j = jt * 8 + (l >> 2);
            #define BIAS(k) coeffs[(size_t)(r * 32 + (k)) * (129 * 64) + 128 * 64 + j]
            uint32_t b0 = bf2(BIAS(K0),     BIAS(K0 + 1));
            uint32_t b1 = bf2(BIAS(K0 + 8), BIAS(K0 + 9));
            #undef BIAS
            ull v; asm("mov.b64 %0, {%1, %2};" : "=l"(v) : "r"(b0), "r"(b1));
            bdst[idx] = v;
        }
    }
}

// ---------------------------------------------------------------------------
// Kernel 4: main combine. Grid (32, 8), 256 thr (8 warps), 128 rows/CTA.
// 3-stage cp.async pipeline, ONE barrier per rule iteration.
// ---------------------------------------------------------------------------
#define STAGE_B 16384
__global__ void __launch_bounds__(256, 2) main_mma_kernel(const float* __restrict__ X) {
    extern __shared__ char smc[];
    ull*   Bbuf = (ull*)smc;                           // 3 x 16 KB
    float* Ns   = (float*)(smc + 3 * STAGE_B);         // [128][33]

    const int tid  = threadIdx.x;
    const int w    = tid >> 5;
    const int lane = tid & 31;
    const int gr   = lane >> 2;
    const int gc   = lane & 3;
    const int nb   = blockIdx.x * 128;
    const int sp   = blockIdx.y;
    const int rb   = sp * 32;

    for (int i = tid; i < 128 * 32; i += 256) {
        int n = i >> 5, rl = i & 31;
        Ns[n * 33 + rl] = g_norm[(size_t)(nb + n) * R_ + rb + rl];
    }

    const int rA = 16 * w + gr;
    const int rB = rA + 8;
    uint32_t xA0[8], xA1[8], xB0[8], xB1[8];
    {
        const float* pa = X + (size_t)(nb + rA) * D_ + 2 * gc;
        const float* pb = X + (size_t)(nb + rB) * D_ + 2 * gc;
        #pragma unroll
        for (int kk = 0; kk < 8; ++kk) {
            float2 v;
            v = *(const float2*)(pa + 16 * kk);     xA0[kk] = bf2(v.x, v.y);
            v = *(const float2*)(pa + 16 * kk + 8); xA1[kk] = bf2(v.x, v.y);
            v = *(const float2*)(pb + 16 * kk);     xB0[kk] = bf2(v.x, v.y);
            v = *(const float2*)(pb + 16 * kk + 8); xB1[kk] = bf2(v.x, v.y);
        }
    }

    const uint32_t bsm = smem_u32(Bbuf);

    // prologue: stage rules 0 and 1
    #pragma unroll
    for (int s = 0; s < 2; ++s) {
        const ull* src = g_Bh + (size_t)(rb + s) * 2048;
        const uint32_t dst = bsm + s * STAGE_B;
        #pragma unroll
        for (int q = 0; q < 4; ++q) {
            int c16 = tid + q * 256;
            asm volatile("cp.async.cg.shared.global [%0], [%1], 16;"
                         :: "r"(dst + c16 * 16), "l"(src + c16 * 2) : "memory");
        }
        asm volatile("cp.async.commit_group;" ::: "memory");
    }

    float acc[8][4];
    #pragma unroll
    for (int jt = 0; jt < 8; ++jt)
        #pragma unroll
        for (int q = 0; q < 4; ++q) acc[jt][q] = 0.0f;

    int buf = 0;
    for (int rr = 0; rr < 32; ++rr) {
        if (rr < 31) asm volatile("cp.async.wait_group 1;" ::: "memory");
        else         asm volatile("cp.async.wait_group 0;" ::: "memory");
        __syncthreads();   // rule rr visible to all; separates prior reads from next overwrite

        if (rr + 2 < 32) {  // prefetch rule rr+2 into buffer (rr+2)%3
            const ull* src = g_Bh + (size_t)(rb + rr + 2) * 2048;
            int b2 = buf + 2; if (b2 >= 3) b2 -= 3;
            const uint32_t dst = bsm + b2 * STAGE_B;
            #pragma unroll
            for (int q = 0; q < 4; ++q) {
                int c16 = tid + q * 256;
                asm volatile("cp.async.cg.shared.global [%0], [%1], 16;"
                             :: "r"(dst + c16 * 16), "l"(src + c16 * 2) : "memory");
            }
            asm volatile("cp.async.commit_group;" ::: "memory");
        }

        const float nA = Ns[rA * 33 + rr];
        const float nB = Ns[rB * 33 + rr];
        const uint32_t n2A = bf2(nA, nA);
        const uint32_t n2B = bf2(nB, nB);
        const ull* bb = Bbuf + buf * 2048 + lane;

        #pragma unroll
        for (int kk = 0; kk < 8; ++kk) {
            uint32_t a0 = hmul2(xA0[kk], n2A);
            uint32_t a1 = hmul2(xB0[kk], n2B);
            uint32_t a2 = hmul2(xA1[kk], n2A);
            uint32_t a3 = hmul2(xB1[kk], n2B);
            #pragma unroll
            for (int jt = 0; jt < 8; ++jt) {
                ull bv = bb[(kk * 8 + jt) * 32];
                uint32_t b0, b1;
                u64lohi(bv, b0, b1);
                mma_bf16(acc[jt], a0, a1, a2, a3, b0, b1);
            }
        }
        if (++buf == 3) buf = 0;
    }

    // ---- bias: 2 extra k16 steps, A = norm fragments, B from g_Bbh (L2)
    {
        const ull* bb = g_Bbh + (size_t)sp * 512 + lane;
        #pragma unroll
        for (int kk = 0; kk < 2; ++kk) {
            const int K0 = kk * 16 + 2 * gc;
            uint32_t a0 = bf2(Ns[rA * 33 + K0],     Ns[rA * 33 + K0 + 1]);
            uint32_t a1 = bf2(Ns[rB * 33 + K0],     Ns[rB * 33 + K0 + 1]);
            uint32_t a2 = bf2(Ns[rA * 33 + K0 + 8], Ns[rA * 33 + K0 + 9]);
            uint32_t a3 = bf2(Ns[rB * 33 + K0 + 8], Ns[rB * 33 + K0 + 9]);
            #pragma unroll
            for (int jt = 0; jt < 8; ++jt) {
                ull bv = bb[(kk * 8 + jt) * 32];
                uint32_t b0, b1;
                u64lohi(bv, b0, b1);
                mma_bf16(acc[jt], a0, a1, a2, a3, b0, b1);
            }
        }
    }

    float* op = g_partial[sp];
    #pragma unroll
    for (int jt = 0; jt < 8; ++jt) {
        const int c = jt * 8 + 2 * gc;
        *(float2*)(op + (size_t)(nb + rA) * O_ + c) = make_float2(acc[jt][0], acc[jt][1]);
        *(float2*)(op + (size_t)(nb + rB) * O_ + c) = make_float2(acc[jt][2], acc[jt][3]);
    }
}

// ---------------------------------------------------------------------------
// Kernel 5: softmax, warp per row (pure shfl), 8 rows/block.
// ---------------------------------------------------------------------------
__global__ void __launch_bounds__(256) softmax_kernel(float* __restrict__ out) {
    const int lane = threadIdx.x & 31;
    const int n = blockIdx.x * 8 + (threadIdx.x >> 5);
    const size_t base = (size_t)n * O_;

    float l0 = 0.0f, l1 = 0.0f;
    #pragma unroll
    for (int s = 0; s < 8; ++s) {
        l0 += g_partial[s][base + lane];
        l1 += g_partial[s][base + lane + 32];
    }
    float m = fmaxf(l0, l1);
    #pragma unroll
    for (int o = 16; o > 0; o >>= 1) m = fmaxf(m, __shfl_xor_sync(0xffffffff, m, o));
    float e0 = expf(l0 - m), e1 = expf(l1 - m);
    float s = e0 + e1;
    #pragma unroll
    for (int o = 16; o > 0; o >>= 1) s += __shfl_xor_sync(0xffffffff, s, o);
    float inv = 1.0f / s;
    out[base + lane]      = e0 * inv;
    out[base + lane + 32] = e1 * inv;
}

// ---------------------------------------------------------------------------
extern "C" void kernel_launch(void* const* d_in, const int* in_sizes, int n_in,
                              void* d_out, int out_size) {
    const float* X       = (const float*)d_in[0];
    const float* centers = (const float*)d_in[1];
    const float* sigmas  = (const float*)d_in[2];
    const float* coeffs  = (const float*)d_in[3];
    float* out = (float*)d_out;

    const int SMEM_M = 3 * STAGE_B + 128 * 33 * (int)sizeof(float);   // 66048 B
    cudaFuncSetAttribute(main_mma_kernel, cudaFuncAttributeMaxDynamicSharedMemorySize, SMEM_M);

    prep_kernel<<<R_, D_>>>(centers, sigmas);                 // 0
    strengths_kernel<<<N_ / 8, 256>>>(X);                     // 1
    prep_bh_kernel<<<R_, 256>>>(coeffs);                      // 2
    main_mma_kernel<<<dim3(N_ / 128, 8), 256, SMEM_M>>>(X);   // 3  <- ncu capture slot
    softmax_kernel<<<N_ / 8, 256>>>(out);                     // 4
}